// round 1
// baseline (speedup 1.0000x reference)
#include <cuda_runtime.h>
#include <cuda_bf16.h>

#define N_CLASSES 26
#define IMG 68
#define BATCH 8192
#define NEXP 64
#define FC1N 500
#define FLATN 1960

// scratch (device globals; no allocation allowed)
__device__ __align__(16) float g_p1[N_CLASSES * 5 * 32 * 32];
__device__ __align__(16) float g_hcls[N_CLASSES * FLATN];
__device__ __align__(16) float g_u[N_CLASSES * FC1N];
__device__ __align__(16) float2 g_wx[FC1N];

// ---------------------------------------------------------------------------
// Kernel A1: conv1 (5x5, 1->5) + relu + maxpool2 per (class, channel)
// grid = 26*5, block = 256. out: g_p1[c][ch][32][32]
// ---------------------------------------------------------------------------
__global__ void conv1_kernel(const float* __restrict__ images,
                             const float* __restrict__ w1,
                             const float* __restrict__ b1) {
    __shared__ float s_img[IMG * IMG];
    __shared__ float s_w[25];
    int c = blockIdx.x / 5, ch = blockIdx.x % 5;
    int tid = threadIdx.x;
    const float* img = images + c * IMG * IMG;
    for (int i = tid; i < IMG * IMG; i += 256) s_img[i] = img[i];
    if (tid < 25) s_w[tid] = w1[ch * 25 + tid];
    __syncthreads();
    float bb = b1[ch];
    float wr[25];
#pragma unroll
    for (int i = 0; i < 25; i++) wr[i] = s_w[i];
    float* outp = g_p1 + (c * 5 + ch) * 1024;
    for (int i = tid; i < 1024; i += 256) {
        int oy = i >> 5, ox = i & 31;
        float m = 0.f;  // max(relu(a..d)) == max(0, a..d)
#pragma unroll
        for (int dy = 0; dy < 2; dy++)
#pragma unroll
            for (int dx = 0; dx < 2; dx++) {
                int y0 = 2 * oy + dy, x0 = 2 * ox + dx;
                float acc = bb;
#pragma unroll
                for (int ky = 0; ky < 5; ky++)
#pragma unroll
                    for (int kx = 0; kx < 5; kx++)
                        acc = fmaf(s_img[(y0 + ky) * IMG + x0 + kx], wr[ky * 5 + kx], acc);
                m = fmaxf(m, acc);
            }
        outp[i] = m;
    }
}

// ---------------------------------------------------------------------------
// Kernel A2: conv2 (5x5, 5->10) + relu + maxpool2 per (class, out-channel)
// grid = 26*10, block = 256. out: g_hcls[c][co*196 + oy*14 + ox]
// ---------------------------------------------------------------------------
__global__ void conv2_kernel(const float* __restrict__ w2,
                             const float* __restrict__ b2) {
    __shared__ float s_p1[5 * 1024];
    __shared__ float s_w[125];
    int c = blockIdx.x / 10, co = blockIdx.x % 10;
    int tid = threadIdx.x;
    for (int i = tid; i < 5120; i += 256) s_p1[i] = g_p1[c * 5120 + i];
    if (tid < 125) s_w[tid] = w2[co * 125 + tid];
    __syncthreads();
    float bb = b2[co];
    for (int i = tid; i < 196; i += 256) {
        int oy = i / 14, ox = i % 14;
        float m = 0.f;
#pragma unroll
        for (int dy = 0; dy < 2; dy++)
#pragma unroll
            for (int dx = 0; dx < 2; dx++) {
                int y0 = 2 * oy + dy, x0 = 2 * ox + dx;
                float acc = bb;
#pragma unroll
                for (int ci = 0; ci < 5; ci++) {
                    const float* base = s_p1 + ci * 1024 + y0 * 32 + x0;
                    const float* wb = s_w + ci * 25;
#pragma unroll
                    for (int ky = 0; ky < 5; ky++)
#pragma unroll
                        for (int kx = 0; kx < 5; kx++)
                            acc = fmaf(base[ky * 32 + kx], wb[ky * 5 + kx], acc);
                }
                m = fmaxf(m, acc);
            }
        g_hcls[c * FLATN + co * 196 + i] = m;
    }
}

// ---------------------------------------------------------------------------
// Kernel B: u[c][out] = fc1_b[out] + sum_k hcls[c][k] * fc1_w[out][k]
// grid = 63 (8 outs per block), block = 256 (8 warps).
// warp-per-(out,cls) dot; fc1 rows staged in smem; hcls rows L1-resident
// (all 8 warps read the same cls row at the same time).
// Also extracts the x-columns of fc1_w into g_wx.
// ---------------------------------------------------------------------------
#define ROWPAD 1964
__global__ void fc1_kernel(const float* __restrict__ fc1_w,
                           const float* __restrict__ fc1_b) {
    extern __shared__ float rows[];  // [8][ROWPAD]
    int tid = threadIdx.x, lane = tid & 31, warp = tid >> 5;
    int o0 = blockIdx.x * 8;
    for (int i = tid; i < 8 * 1962; i += 256) {
        int r = i / 1962, k = i - r * 1962;
        int out = o0 + r;
        rows[r * ROWPAD + k] = (out < FC1N) ? fc1_w[out * 1962 + k] : 0.f;
    }
    __syncthreads();
    for (int p = warp; p < 8 * N_CLASSES; p += 8) {
        int cls = p >> 3, outL = p & 7;
        int out = o0 + outL;
        const float4* hc = (const float4*)(g_hcls + cls * FLATN);
        const float4* wr = (const float4*)(rows + outL * ROWPAD);
        float acc = 0.f;
        for (int k4 = lane; k4 < 490; k4 += 32) {
            float4 h = hc[k4], w = wr[k4];
            acc += h.x * w.x + h.y * w.y + h.z * w.z + h.w * w.w;
        }
#pragma unroll
        for (int off = 16; off; off >>= 1) acc += __shfl_xor_sync(~0u, acc, off);
        if (lane == 0 && out < FC1N) g_u[cls * FC1N + out] = acc + fc1_b[out];
    }
    if (tid < 8) {
        int out = o0 + tid;
        if (out < FC1N) {
            float2 v;
            v.x = rows[tid * ROWPAD + 1960];
            v.y = rows[tid * ROWPAD + 1961];
            g_wx[out] = v;
        }
    }
}

// ---------------------------------------------------------------------------
// Kernel C: fused per-sample pipeline.
// grid = 128 blocks x 64 samples, block = 256.
//   1) hT[k][s] = relu(u[cls[s]][k] + x0*wx0[k] + x1*wx1[k])   (two k-halves)
//   2) logits[64][64] = hT^T @ w2s  (register-tiled, packed f32x2 FMA)
//   3) softmax over 64 experts + expert mix  s = (1/Z) sum_n e_n * A_n @ diff
// smem: hT[250][68] + w2s[500][68] + Ls[64][68] + small  = ~224 KB
// ---------------------------------------------------------------------------
#define TS 64
#define HPAD 68
#define KSLAB 250
#define SMEMC ((KSLAB * HPAD + FC1N * HPAD + TS * HPAD + 256 + 64 + 4 * 64 + 64) * 4)

__global__ void __launch_bounds__(256, 1)
moe_kernel(const float* __restrict__ x, const int* __restrict__ cls_idx,
           const float* __restrict__ fc2_w, const float* __restrict__ fc2_b,
           const float* __restrict__ A_B, const float* __restrict__ A_C,
           const float* __restrict__ x_tar, float* __restrict__ out) {
    extern __shared__ float sm[];
    float* hT  = sm;                   // [KSLAB][HPAD]
    float* w2s = hT + KSLAB * HPAD;    // [FC1N][HPAD] (k-major, transposed)
    float* Ls  = w2s + FC1N * HPAD;    // [TS][HPAD]
    float* Gs  = Ls + TS * HPAD;       // [64][4] = A_B + A_C
    float* b2s = Gs + 256;             // [64]
    float* sx0 = b2s + 64;
    float* sx1 = sx0 + 64;
    float* sd0 = sx1 + 64;
    float* sd1 = sd0 + 64;
    int*   scls = (int*)(sd1 + 64);

    int tid = threadIdx.x, lane = tid & 31, warp = tid >> 5;
    int base = blockIdx.x * TS;

    // transpose-load fc2_w into smem: w2s[k][e]
    for (int i = tid; i < NEXP * FC1N; i += 256) {
        int e = i / FC1N, k = i - e * FC1N;
        w2s[k * HPAD + e] = fc2_w[i];
    }
    if (tid < 256) Gs[tid] = A_B[tid] + A_C[tid];
    if (tid < 64) b2s[tid] = fc2_b[tid];
    if (tid < TS) {
        int s = base + tid;
        float x0v = x[2 * s], x1v = x[2 * s + 1];
        sx0[tid] = x0v; sx1[tid] = x1v;
        sd0[tid] = x_tar[0] - x0v;
        sd1[tid] = x_tar[1] - x1v;
        scls[tid] = cls_idx[s];
    }
    __syncthreads();

    int tx = tid & 15, ty = tid >> 4;  // experts 4tx..4tx+3, samples 4ty..4ty+3
    unsigned long long acc[2][4];
#pragma unroll
    for (int i = 0; i < 2; i++)
#pragma unroll
        for (int j = 0; j < 4; j++) acc[i][j] = 0ull;

    for (int half = 0; half < 2; half++) {
        int kb = half * KSLAB;
        // fill hT slab: warp-per-sample, coalesced u reads
        for (int s = warp; s < TS; s += 8) {
            int cls = scls[s];
            float xx0 = sx0[s], xx1 = sx1[s];
            const float* urow = g_u + cls * FC1N + kb;
            for (int k = lane; k < KSLAB; k += 32) {
                float2 wv = g_wx[kb + k];
                float v = fmaf(xx0, wv.x, fmaf(xx1, wv.y, urow[k]));
                hT[k * HPAD + s] = fmaxf(v, 0.f);
            }
        }
        __syncthreads();

        const float* w2p = w2s + kb * HPAD;
#pragma unroll 2
        for (int k = 0; k < KSLAB; k++) {
            float4 h4 = *(const float4*)(hT + k * HPAD + 4 * ty);
            float4 w4 = *(const float4*)(w2p + k * HPAD + 4 * tx);
            unsigned long long hp0, hp1, wdx, wdy, wdz, wdw;
            asm("mov.b64 %0, {%1,%2};" : "=l"(hp0) : "f"(h4.x), "f"(h4.y));
            asm("mov.b64 %0, {%1,%2};" : "=l"(hp1) : "f"(h4.z), "f"(h4.w));
            asm("mov.b64 %0, {%1,%1};" : "=l"(wdx) : "f"(w4.x));
            asm("mov.b64 %0, {%1,%1};" : "=l"(wdy) : "f"(w4.y));
            asm("mov.b64 %0, {%1,%1};" : "=l"(wdz) : "f"(w4.z));
            asm("mov.b64 %0, {%1,%1};" : "=l"(wdw) : "f"(w4.w));
            asm("fma.rn.f32x2 %0, %1, %2, %0;" : "+l"(acc[0][0]) : "l"(hp0), "l"(wdx));
            asm("fma.rn.f32x2 %0, %1, %2, %0;" : "+l"(acc[1][0]) : "l"(hp1), "l"(wdx));
            asm("fma.rn.f32x2 %0, %1, %2, %0;" : "+l"(acc[0][1]) : "l"(hp0), "l"(wdy));
            asm("fma.rn.f32x2 %0, %1, %2, %0;" : "+l"(acc[1][1]) : "l"(hp1), "l"(wdy));
            asm("fma.rn.f32x2 %0, %1, %2, %0;" : "+l"(acc[0][2]) : "l"(hp0), "l"(wdz));
            asm("fma.rn.f32x2 %0, %1, %2, %0;" : "+l"(acc[1][2]) : "l"(hp1), "l"(wdz));
            asm("fma.rn.f32x2 %0, %1, %2, %0;" : "+l"(acc[0][3]) : "l"(hp0), "l"(wdw));
            asm("fma.rn.f32x2 %0, %1, %2, %0;" : "+l"(acc[1][3]) : "l"(hp1), "l"(wdw));
        }
        __syncthreads();
    }

    // write logits (+bias) to smem
#pragma unroll
    for (int pp = 0; pp < 2; pp++)
#pragma unroll
        for (int j = 0; j < 4; j++) {
            float lo, hi;
            asm("mov.b64 {%0,%1}, %2;" : "=f"(lo), "=f"(hi) : "l"(acc[pp][j]));
            int e = 4 * tx + j;
            float bb = b2s[e];
            Ls[(4 * ty + 2 * pp + 0) * HPAD + e] = lo + bb;
            Ls[(4 * ty + 2 * pp + 1) * HPAD + e] = hi + bb;
        }
    __syncthreads();

    // softmax over 64 + expert mix; warp-per-sample (2 experts per lane)
    for (int s = warp; s < TS; s += 8) {
        float l0 = Ls[s * HPAD + lane];
        float l1 = Ls[s * HPAD + 32 + lane];
        float m = fmaxf(l0, l1);
#pragma unroll
        for (int off = 16; off; off >>= 1) m = fmaxf(m, __shfl_xor_sync(~0u, m, off));
        float e0 = __expf(l0 - m), e1 = __expf(l1 - m);
        float d0 = sd0[s], d1 = sd1[s];
        const float* G0 = Gs + lane * 4;
        const float* G1 = Gs + (lane + 32) * 4;
        float y0 = e0 * (G0[0] * d0 + G0[1] * d1) + e1 * (G1[0] * d0 + G1[1] * d1);
        float y1 = e0 * (G0[2] * d0 + G0[3] * d1) + e1 * (G1[2] * d0 + G1[3] * d1);
        float Z = e0 + e1;
#pragma unroll
        for (int off = 16; off; off >>= 1) {
            y0 += __shfl_xor_sync(~0u, y0, off);
            y1 += __shfl_xor_sync(~0u, y1, off);
            Z  += __shfl_xor_sync(~0u, Z, off);
        }
        if (lane == 0) {
            float inv = 1.f / Z;
            out[2 * (base + s) + 0] = y0 * inv;
            out[2 * (base + s) + 1] = y1 * inv;
        }
    }
}

// ---------------------------------------------------------------------------
extern "C" void kernel_launch(void* const* d_in, const int* in_sizes, int n_in,
                              void* d_out, int out_size) {
    const float* x       = (const float*)d_in[0];
    const int*   cls     = (const int*)d_in[1];
    const float* images  = (const float*)d_in[2];
    const float* conv1_w = (const float*)d_in[3];
    const float* conv1_b = (const float*)d_in[4];
    const float* conv2_w = (const float*)d_in[5];
    const float* conv2_b = (const float*)d_in[6];
    const float* fc1_w   = (const float*)d_in[7];
    const float* fc1_b   = (const float*)d_in[8];
    const float* fc2_w   = (const float*)d_in[9];
    const float* fc2_b   = (const float*)d_in[10];
    const float* A_B     = (const float*)d_in[11];
    const float* A_C     = (const float*)d_in[12];
    const float* x_tar   = (const float*)d_in[13];
    float* out = (float*)d_out;

    cudaFuncSetAttribute(fc1_kernel, cudaFuncAttributeMaxDynamicSharedMemorySize,
                         8 * ROWPAD * 4);
    cudaFuncSetAttribute(moe_kernel, cudaFuncAttributeMaxDynamicSharedMemorySize,
                         SMEMC);

    conv1_kernel<<<N_CLASSES * 5, 256>>>(images, conv1_w, conv1_b);
    conv2_kernel<<<N_CLASSES * 10, 256>>>(conv2_w, conv2_b);
    fc1_kernel<<<63, 256, 8 * ROWPAD * 4>>>(fc1_w, fc1_b);
    moe_kernel<<<BATCH / TS, 256, SMEMC>>>(x, cls, fc2_w, fc2_b, A_B, A_C, x_tar, out);
    (void)in_sizes; (void)n_in; (void)out_size;
}

// round 2
// speedup vs baseline: 2.2076x; 2.2076x over previous
#include <cuda_runtime.h>
#include <cuda_bf16.h>

#define N_CLASSES 26
#define IMG 68
#define BATCH 8192
#define NEXP 64
#define FC1N 500
#define FLATN 1960

// scratch (device globals; no allocation allowed)
__device__ __align__(16) float g_p1[N_CLASSES * 5 * 32 * 32];
__device__ __align__(16) float g_hcls[N_CLASSES * FLATN];
__device__ __align__(16) float g_upart[8 * N_CLASSES * FC1N];
__device__ __align__(16) float g_u[N_CLASSES * FC1N];
__device__ __align__(16) float2 g_wx[FC1N];
__device__ __align__(16) float g_w2t[FC1N * NEXP];   // [k][e]

// ---------------------------------------------------------------------------
// Kernel A1: conv1 (5x5, 1->5) + relu + maxpool2 per (class, channel).
// Also: transpose fc2_w -> g_w2t, extract fc1_w x-columns -> g_wx.
// grid = 130, block = 256.
// ---------------------------------------------------------------------------
__global__ void conv1_kernel(const float* __restrict__ images,
                             const float* __restrict__ w1,
                             const float* __restrict__ b1,
                             const float* __restrict__ fc1_w,
                             const float* __restrict__ fc2_w) {
    __shared__ float s_img[IMG * IMG];
    __shared__ float s_w[25];
    int c = blockIdx.x / 5, ch = blockIdx.x % 5;
    int tid = threadIdx.x;

    // side work: fc2_w transpose + wx extraction (independent of smem)
    int gt = blockIdx.x * 256 + tid;
    if (gt < NEXP * FC1N) {
        int e = gt / FC1N, k = gt - e * FC1N;
        g_w2t[k * NEXP + e] = fc2_w[gt];
    }
    if (gt < FC1N) {
        float2 v;
        v.x = fc1_w[gt * 1962 + 1960];
        v.y = fc1_w[gt * 1962 + 1961];
        g_wx[gt] = v;
    }

    const float* img = images + c * IMG * IMG;
    for (int i = tid; i < IMG * IMG; i += 256) s_img[i] = img[i];
    if (tid < 25) s_w[tid] = w1[ch * 25 + tid];
    __syncthreads();
    float bb = b1[ch];
    float wr[25];
#pragma unroll
    for (int i = 0; i < 25; i++) wr[i] = s_w[i];
    float* outp = g_p1 + (c * 5 + ch) * 1024;
    for (int i = tid; i < 1024; i += 256) {
        int oy = i >> 5, ox = i & 31;
        int y0 = 2 * oy, x0 = 2 * ox;
        float p[6][6];
#pragma unroll
        for (int r = 0; r < 6; r++)
#pragma unroll
            for (int cc = 0; cc < 6; cc++) p[r][cc] = s_img[(y0 + r) * IMG + x0 + cc];
        float a00 = bb, a01 = bb, a10 = bb, a11 = bb;
#pragma unroll
        for (int ky = 0; ky < 5; ky++)
#pragma unroll
            for (int kx = 0; kx < 5; kx++) {
                float w = wr[ky * 5 + kx];
                a00 = fmaf(p[ky][kx], w, a00);
                a01 = fmaf(p[ky][kx + 1], w, a01);
                a10 = fmaf(p[ky + 1][kx], w, a10);
                a11 = fmaf(p[ky + 1][kx + 1], w, a11);
            }
        outp[i] = fmaxf(fmaxf(fmaxf(a00, a01), fmaxf(a10, a11)), 0.f);
    }
}

// ---------------------------------------------------------------------------
// Kernel A2: conv2 (5x5, 5->10) + relu + maxpool2. grid = 260, block = 256.
// ---------------------------------------------------------------------------
__global__ void conv2_kernel(const float* __restrict__ w2,
                             const float* __restrict__ b2) {
    __shared__ float s_p1[5 * 1024];
    __shared__ float s_w[125];
    int c = blockIdx.x / 10, co = blockIdx.x % 10;
    int tid = threadIdx.x;
    for (int i = tid; i < 5120; i += 256) s_p1[i] = g_p1[c * 5120 + i];
    if (tid < 125) s_w[tid] = w2[co * 125 + tid];
    __syncthreads();
    float bb = b2[co];
    for (int i = tid; i < 196; i += 256) {
        int oy = i / 14, ox = i % 14;
        int y0 = 2 * oy, x0 = 2 * ox;
        float a00 = bb, a01 = bb, a10 = bb, a11 = bb;
#pragma unroll
        for (int ci = 0; ci < 5; ci++) {
            const float* base = s_p1 + ci * 1024 + y0 * 32 + x0;
            float p[6][6];
#pragma unroll
            for (int r = 0; r < 6; r++)
#pragma unroll
                for (int cc = 0; cc < 6; cc++) p[r][cc] = base[r * 32 + cc];
            const float* wb = s_w + ci * 25;
#pragma unroll
            for (int ky = 0; ky < 5; ky++)
#pragma unroll
                for (int kx = 0; kx < 5; kx++) {
                    float w = wb[ky * 5 + kx];
                    a00 = fmaf(p[ky][kx], w, a00);
                    a01 = fmaf(p[ky][kx + 1], w, a01);
                    a10 = fmaf(p[ky + 1][kx], w, a10);
                    a11 = fmaf(p[ky + 1][kx + 1], w, a11);
                }
        }
        g_hcls[c * FLATN + co * 196 + i] =
            fmaxf(fmaxf(fmaxf(a00, a01), fmaxf(a10, a11)), 0.f);
    }
}

// ---------------------------------------------------------------------------
// Kernel B: fc1 partial GEMM. u_part[ks][c][out] = sum_{k in slab} h[c][k]*W[out][k]
// grid = 128 (16 out-tiles x 8 k-slabs), block = 256.
// thread = (out=lane within 32-out tile, 4 classes = warp+8j). Deterministic
// (no atomics): partials reduced by fc1_reduce.
// ---------------------------------------------------------------------------
#define KS 245
__global__ void fc1_kernel(const float* __restrict__ fc1_w) {
    extern __shared__ float sm[];
    float* smw = sm;              // [32][245]
    float* smh = smw + 32 * KS;   // [26][245]
    int tid = threadIdx.x, lane = tid & 31, warp = tid >> 5;
    int ob = (blockIdx.x & 15) * 32;
    int ks = blockIdx.x >> 4;
    int kb = ks * KS;
    for (int i = tid; i < 32 * KS; i += 256) {
        int r = i / KS, k = i - r * KS;
        int o = ob + r;
        smw[i] = (o < FC1N) ? fc1_w[o * 1962 + kb + k] : 0.f;
    }
    for (int i = tid; i < 26 * KS; i += 256) {
        int cc = i / KS, k = i - cc * KS;
        smh[i] = g_hcls[cc * FLATN + kb + k];
    }
    __syncthreads();
    int out = ob + lane;
    const float* wp = smw + lane * KS;
    const float* h0 = smh + warp * KS;
    const float* h1 = smh + (warp + 8) * KS;
    const float* h2 = smh + (warp + 16) * KS;
    bool has3 = (warp < 2);
    const float* h3 = smh + (has3 ? (warp + 24) : warp) * KS;
    float a0 = 0.f, a1 = 0.f, a2 = 0.f, a3 = 0.f;
#pragma unroll 5
    for (int k = 0; k < KS; k++) {
        float w = wp[k];
        a0 = fmaf(w, h0[k], a0);
        a1 = fmaf(w, h1[k], a1);
        a2 = fmaf(w, h2[k], a2);
        a3 = fmaf(w, h3[k], a3);
    }
    if (out < FC1N) {
        float* up = g_upart + ks * (N_CLASSES * FC1N);
        up[warp * FC1N + out] = a0;
        up[(warp + 8) * FC1N + out] = a1;
        up[(warp + 16) * FC1N + out] = a2;
        if (has3) up[(warp + 24) * FC1N + out] = a3;
    }
}

// grid = 26, block = 512: g_u = sum of 8 partials + fc1_b
__global__ void fc1_reduce(const float* __restrict__ fc1_b) {
    int i = blockIdx.x * 512 + threadIdx.x;
    if (i < N_CLASSES * FC1N) {
        float s = 0.f;
#pragma unroll
        for (int j = 0; j < 8; j++) s += g_upart[j * (N_CLASSES * FC1N) + i];
        int out = i % FC1N;
        g_u[i] = s + fc1_b[out];
    }
}

// ---------------------------------------------------------------------------
// Kernel C: fused per-sample pipeline. grid = 128 x 64 samples, block = 512.
//   warp <-> 4 samples (h broadcast), lane <-> 2 experts.
//   smem: w2s[500][64] + hT[250][68] + Ls[64][68] + wxs + misc ~ 215 KB
// ---------------------------------------------------------------------------
#define TS 64
#define HPAD 68
#define KSLAB 250
#define SMEMC ((FC1N * NEXP + KSLAB * HPAD + TS * HPAD + 2 * FC1N + 256 + 64 * 5 + 64) * 4)

__global__ void __launch_bounds__(512, 1)
moe_kernel(const float* __restrict__ x, const int* __restrict__ cls_idx,
           const float* __restrict__ fc2_b,
           const float* __restrict__ A_B, const float* __restrict__ A_C,
           const float* __restrict__ x_tar, float* __restrict__ out) {
    extern __shared__ float sm[];
    float* w2s = sm;                       // [500][64] (k-major)
    float* hT  = w2s + FC1N * NEXP;        // [250][68]
    float* Ls  = hT + KSLAB * HPAD;        // [64][68]
    float2* wxs = (float2*)(Ls + TS * HPAD);  // [500]
    float* Gs  = (float*)(wxs + FC1N);     // [64][4]
    float* b2s = Gs + 256;
    float* sx0 = b2s + 64;
    float* sx1 = sx0 + 64;
    float* sd0 = sx1 + 64;
    float* sd1 = sd0 + 64;
    int*   scls = (int*)(sd1 + 64);

    int tid = threadIdx.x, lane = tid & 31, warp = tid >> 5;  // 16 warps
    int base = blockIdx.x * TS;

    // coalesced copy of pre-transposed fc2_w
    {
        const float4* src = (const float4*)g_w2t;
        float4* dst = (float4*)w2s;
        for (int i = tid; i < (FC1N * NEXP) / 4; i += 512) dst[i] = src[i];
    }
    for (int i = tid; i < FC1N; i += 512) wxs[i] = g_wx[i];
    if (tid < 256) Gs[tid] = A_B[tid] + A_C[tid];
    if (tid < 64) b2s[tid] = fc2_b[tid];
    if (tid < TS) {
        int s = base + tid;
        float x0v = x[2 * s], x1v = x[2 * s + 1];
        sx0[tid] = x0v; sx1[tid] = x1v;
        sd0[tid] = x_tar[0] - x0v;
        sd1[tid] = x_tar[1] - x1v;
        scls[tid] = cls_idx[s];
    }
    __syncthreads();

    unsigned long long acc[2][2];  // [expert e][sample-pair p]
#pragma unroll
    for (int i = 0; i < 2; i++)
#pragma unroll
        for (int j = 0; j < 2; j++) acc[i][j] = 0ull;

    for (int half = 0; half < 2; half++) {
        int kb = half * KSLAB;
        // fill hT slab: warp-per-sample, coalesced u reads (bias folded into g_u)
        for (int s = warp; s < TS; s += 16) {
            int cls = scls[s];
            float xx0 = sx0[s], xx1 = sx1[s];
            const float* urow = g_u + cls * FC1N + kb;
            for (int k = lane; k < KSLAB; k += 32) {
                float2 wv = wxs[kb + k];
                float v = fmaf(xx0, wv.x, fmaf(xx1, wv.y, urow[k]));
                hT[k * HPAD + s] = fmaxf(v, 0.f);
            }
        }
        __syncthreads();

        const float* hp = hT + 4 * warp;            // broadcast per warp
        const float* wp = w2s + kb * NEXP + 2 * lane;
#pragma unroll 5
        for (int k = 0; k < KSLAB; k++) {
            float4 h4 = *(const float4*)(hp + k * HPAD);
            float2 w2 = *(const float2*)(wp + k * NEXP);
            unsigned long long hp0, hp1, wd0, wd1;
            asm("mov.b64 %0, {%1,%2};" : "=l"(hp0) : "f"(h4.x), "f"(h4.y));
            asm("mov.b64 %0, {%1,%2};" : "=l"(hp1) : "f"(h4.z), "f"(h4.w));
            asm("mov.b64 %0, {%1,%1};" : "=l"(wd0) : "f"(w2.x));
            asm("mov.b64 %0, {%1,%1};" : "=l"(wd1) : "f"(w2.y));
            asm("fma.rn.f32x2 %0, %1, %2, %0;" : "+l"(acc[0][0]) : "l"(hp0), "l"(wd0));
            asm("fma.rn.f32x2 %0, %1, %2, %0;" : "+l"(acc[0][1]) : "l"(hp1), "l"(wd0));
            asm("fma.rn.f32x2 %0, %1, %2, %0;" : "+l"(acc[1][0]) : "l"(hp0), "l"(wd1));
            asm("fma.rn.f32x2 %0, %1, %2, %0;" : "+l"(acc[1][1]) : "l"(hp1), "l"(wd1));
        }
        __syncthreads();
    }

    // logits (+bias) to smem: samples 4*warp+2p(+1), expert 2*lane+e
#pragma unroll
    for (int e = 0; e < 2; e++)
#pragma unroll
        for (int p = 0; p < 2; p++) {
            float lo, hi;
            asm("mov.b64 {%0,%1}, %2;" : "=f"(lo), "=f"(hi) : "l"(acc[e][p]));
            int E = 2 * lane + e;
            float bb = b2s[E];
            Ls[(4 * warp + 2 * p + 0) * HPAD + E] = lo + bb;
            Ls[(4 * warp + 2 * p + 1) * HPAD + E] = hi + bb;
        }
    __syncthreads();

    // softmax over 64 + expert mix; warp-per-sample (2 experts per lane)
    for (int s = warp; s < TS; s += 16) {
        float l0 = Ls[s * HPAD + lane];
        float l1 = Ls[s * HPAD + 32 + lane];
        float m = fmaxf(l0, l1);
#pragma unroll
        for (int off = 16; off; off >>= 1) m = fmaxf(m, __shfl_xor_sync(~0u, m, off));
        float e0 = __expf(l0 - m), e1 = __expf(l1 - m);
        float d0 = sd0[s], d1 = sd1[s];
        const float* G0 = Gs + lane * 4;
        const float* G1 = Gs + (lane + 32) * 4;
        float y0 = e0 * (G0[0] * d0 + G0[1] * d1) + e1 * (G1[0] * d0 + G1[1] * d1);
        float y1 = e0 * (G0[2] * d0 + G0[3] * d1) + e1 * (G1[2] * d0 + G1[3] * d1);
        float Z = e0 + e1;
#pragma unroll
        for (int off = 16; off; off >>= 1) {
            y0 += __shfl_xor_sync(~0u, y0, off);
            y1 += __shfl_xor_sync(~0u, y1, off);
            Z  += __shfl_xor_sync(~0u, Z, off);
        }
        if (lane == 0) {
            float inv = 1.f / Z;
            out[2 * (base + s) + 0] = y0 * inv;
            out[2 * (base + s) + 1] = y1 * inv;
        }
    }
}

// ---------------------------------------------------------------------------
extern "C" void kernel_launch(void* const* d_in, const int* in_sizes, int n_in,
                              void* d_out, int out_size) {
    const float* x       = (const float*)d_in[0];
    const int*   cls     = (const int*)d_in[1];
    const float* images  = (const float*)d_in[2];
    const float* conv1_w = (const float*)d_in[3];
    const float* conv1_b = (const float*)d_in[4];
    const float* conv2_w = (const float*)d_in[5];
    const float* conv2_b = (const float*)d_in[6];
    const float* fc1_w   = (const float*)d_in[7];
    const float* fc1_b   = (const float*)d_in[8];
    const float* fc2_w   = (const float*)d_in[9];
    const float* fc2_b   = (const float*)d_in[10];
    const float* A_B     = (const float*)d_in[11];
    const float* A_C     = (const float*)d_in[12];
    const float* x_tar   = (const float*)d_in[13];
    float* out = (float*)d_out;

    cudaFuncSetAttribute(fc1_kernel, cudaFuncAttributeMaxDynamicSharedMemorySize,
                         (32 * KS + 26 * KS) * 4);
    cudaFuncSetAttribute(moe_kernel, cudaFuncAttributeMaxDynamicSharedMemorySize,
                         SMEMC);

    conv1_kernel<<<N_CLASSES * 5, 256>>>(images, conv1_w, conv1_b, fc1_w, fc2_w);
    conv2_kernel<<<N_CLASSES * 10, 256>>>(conv2_w, conv2_b);
    fc1_kernel<<<128, 256, (32 * KS + 26 * KS) * 4>>>(fc1_w);
    fc1_reduce<<<N_CLASSES, 512>>>(fc1_b);
    moe_kernel<<<BATCH / TS, 512, SMEMC>>>(x, cls, fc2_b, A_B, A_C, x_tar, out);
    (void)in_sizes; (void)n_in; (void)out_size;
}

// round 3
// speedup vs baseline: 2.4748x; 1.1210x over previous
#include <cuda_runtime.h>
#include <cuda_bf16.h>

#define N_CLASSES 26
#define IMG 68
#define BATCH 8192
#define NEXP 64
#define FC1N 500
#define FLATN 1960

// scratch (device globals; no allocation allowed)
__device__ __align__(16) float g_p1[N_CLASSES * 5 * 32 * 32];
__device__ __align__(16) float g_hcls[N_CLASSES * FLATN];
__device__ __align__(16) float g_u[N_CLASSES * FC1N];
__device__ __align__(16) float2 g_wx[FC1N];

// ---------------------------------------------------------------------------
// Kernel A1: conv1 (5x5, 1->5) + relu + maxpool2 per (class, channel).
// Also: extract fc1_w x-columns -> g_wx. grid = 130, block = 512.
// ---------------------------------------------------------------------------
__global__ void conv1_kernel(const float* __restrict__ images,
                             const float* __restrict__ w1,
                             const float* __restrict__ b1,
                             const float* __restrict__ fc1_w) {
    __shared__ float s_img[IMG * IMG];
    __shared__ float s_w[25];
    int c = blockIdx.x / 5, ch = blockIdx.x % 5;
    int tid = threadIdx.x;

    int gt = blockIdx.x * 512 + tid;
    if (gt < FC1N) {
        float2 v;
        v.x = fc1_w[gt * 1962 + 1960];
        v.y = fc1_w[gt * 1962 + 1961];
        g_wx[gt] = v;
    }

    const float* img = images + c * IMG * IMG;
    for (int i = tid; i < IMG * IMG; i += 512) s_img[i] = img[i];
    if (tid < 25) s_w[tid] = w1[ch * 25 + tid];
    __syncthreads();
    float bb = b1[ch];
    float wr[25];
#pragma unroll
    for (int i = 0; i < 25; i++) wr[i] = s_w[i];
    float* outp = g_p1 + (c * 5 + ch) * 1024;
    for (int i = tid; i < 1024; i += 512) {
        int oy = i >> 5, ox = i & 31;
        int y0 = 2 * oy, x0 = 2 * ox;
        float p[6][6];
#pragma unroll
        for (int r = 0; r < 6; r++)
#pragma unroll
            for (int cc = 0; cc < 6; cc++) p[r][cc] = s_img[(y0 + r) * IMG + x0 + cc];
        float a00 = bb, a01 = bb, a10 = bb, a11 = bb;
#pragma unroll
        for (int ky = 0; ky < 5; ky++)
#pragma unroll
            for (int kx = 0; kx < 5; kx++) {
                float w = wr[ky * 5 + kx];
                a00 = fmaf(p[ky][kx], w, a00);
                a01 = fmaf(p[ky][kx + 1], w, a01);
                a10 = fmaf(p[ky + 1][kx], w, a10);
                a11 = fmaf(p[ky + 1][kx + 1], w, a11);
            }
        outp[i] = fmaxf(fmaxf(fmaxf(a00, a01), fmaxf(a10, a11)), 0.f);
    }
}

// ---------------------------------------------------------------------------
// Kernel A2: conv2 (5x5, 5->10) + relu + maxpool2. grid = 260, block = 256.
// ---------------------------------------------------------------------------
__global__ void conv2_kernel(const float* __restrict__ w2,
                             const float* __restrict__ b2) {
    __shared__ float s_p1[5 * 1024];
    __shared__ float s_w[125];
    int c = blockIdx.x / 10, co = blockIdx.x % 10;
    int tid = threadIdx.x;
    for (int i = tid; i < 5120; i += 256) s_p1[i] = g_p1[c * 5120 + i];
    if (tid < 125) s_w[tid] = w2[co * 125 + tid];
    __syncthreads();
    float bb = b2[co];
    for (int i = tid; i < 196; i += 256) {
        int oy = i / 14, ox = i % 14;
        int y0 = 2 * oy, x0 = 2 * ox;
        float a00 = bb, a01 = bb, a10 = bb, a11 = bb;
#pragma unroll
        for (int ci = 0; ci < 5; ci++) {
            const float* base = s_p1 + ci * 1024 + y0 * 32 + x0;
            float p[6][6];
#pragma unroll
            for (int r = 0; r < 6; r++)
#pragma unroll
                for (int cc = 0; cc < 6; cc++) p[r][cc] = base[r * 32 + cc];
            const float* wb = s_w + ci * 25;
#pragma unroll
            for (int ky = 0; ky < 5; ky++)
#pragma unroll
                for (int kx = 0; kx < 5; kx++) {
                    float w = wb[ky * 5 + kx];
                    a00 = fmaf(p[ky][kx], w, a00);
                    a01 = fmaf(p[ky][kx + 1], w, a01);
                    a10 = fmaf(p[ky + 1][kx], w, a10);
                    a11 = fmaf(p[ky + 1][kx + 1], w, a11);
                }
        }
        g_hcls[c * FLATN + co * 196 + i] =
            fmaxf(fmaxf(fmaxf(a00, a01), fmaxf(a10, a11)), 0.f);
    }
}

// ---------------------------------------------------------------------------
// Kernel B: fc1, single kernel, no k-split / no reduce kernel.
// grid = 32 out-tiles(16) x 4 class-tiles(8) = 128 blocks, block = 256.
// thread = (o in 16, cg in 2 -> 4 classes, kq8 in 8 -> strided k-quads).
// smem: W tile 16x1964 + h tile 8x1964 + 1024 partials = ~193 KB.
// ---------------------------------------------------------------------------
#define WROWP 1964
#define FC1SMEM ((16 * WROWP + 8 * WROWP + 1024) * 4)
__global__ void __launch_bounds__(256, 1) fc1_kernel(const float* __restrict__ fc1_w,
                                                     const float* __restrict__ fc1_b) {
    extern __shared__ float sm[];
    float* smW = sm;                    // [16][1964]
    float* smH = smW + 16 * WROWP;      // [8][1964]
    float* pbuf = smH + 8 * WROWP;      // [1024]
    int tid = threadIdx.x;
    int ot = blockIdx.x & 31, ct = blockIdx.x >> 5;

    // stage W: 16 rows x 1960 (float2: fc1_w rows are 8B-aligned)
    for (int idx = tid; idx < 16 * 980; idx += 256) {
        int r = idx / 980, k2 = idx - r * 980;
        int row = ot * 16 + r;
        float2 v = (row < FC1N)
                       ? ((const float2*)(fc1_w + (long)row * 1962))[k2]
                       : make_float2(0.f, 0.f);
        *(float2*)(smW + r * WROWP + 2 * k2) = v;
    }
    // stage h: 8 class rows (float4)
    for (int idx = tid; idx < 8 * 490; idx += 256) {
        int r = idx / 490, q = idx - r * 490;
        int ci = ct * 8 + r;
        float4 v = (ci < N_CLASSES)
                       ? ((const float4*)(g_hcls + ci * FLATN))[q]
                       : make_float4(0.f, 0.f, 0.f, 0.f);
        *(float4*)(smH + r * WROWP + 4 * q) = v;
    }
    __syncthreads();

    int o = tid & 15, cg = (tid >> 4) & 1, kq8 = tid >> 5;
    const float4* wq = (const float4*)(smW + o * WROWP);
    const float4* h0 = (const float4*)(smH + (4 * cg + 0) * WROWP);
    const float4* h1 = (const float4*)(smH + (4 * cg + 1) * WROWP);
    const float4* h2 = (const float4*)(smH + (4 * cg + 2) * WROWP);
    const float4* h3 = (const float4*)(smH + (4 * cg + 3) * WROWP);
    float a0 = 0.f, a1 = 0.f, a2 = 0.f, a3 = 0.f;
    for (int q = kq8; q < 490; q += 8) {
        float4 w = wq[q];
        float4 v0 = h0[q], v1 = h1[q], v2 = h2[q], v3 = h3[q];
        a0 = fmaf(w.x, v0.x, a0); a0 = fmaf(w.y, v0.y, a0);
        a0 = fmaf(w.z, v0.z, a0); a0 = fmaf(w.w, v0.w, a0);
        a1 = fmaf(w.x, v1.x, a1); a1 = fmaf(w.y, v1.y, a1);
        a1 = fmaf(w.z, v1.z, a1); a1 = fmaf(w.w, v1.w, a1);
        a2 = fmaf(w.x, v2.x, a2); a2 = fmaf(w.y, v2.y, a2);
        a2 = fmaf(w.z, v2.z, a2); a2 = fmaf(w.w, v2.w, a2);
        a3 = fmaf(w.x, v3.x, a3); a3 = fmaf(w.y, v3.y, a3);
        a3 = fmaf(w.z, v3.z, a3); a3 = fmaf(w.w, v3.w, a3);
    }
    pbuf[o + 16 * (4 * cg + 0) + 128 * kq8] = a0;
    pbuf[o + 16 * (4 * cg + 1) + 128 * kq8] = a1;
    pbuf[o + 16 * (4 * cg + 2) + 128 * kq8] = a2;
    pbuf[o + 16 * (4 * cg + 3) + 128 * kq8] = a3;
    __syncthreads();
    if (tid < 128) {
        int oo = tid & 15, c = tid >> 4;
        float s = 0.f;
#pragma unroll
        for (int j = 0; j < 8; j++) s += pbuf[oo + 16 * c + 128 * j];
        int cls = ct * 8 + c;
        int out = ot * 16 + oo;
        if (cls < N_CLASSES && out < FC1N)
            g_u[cls * FC1N + out] = s + fc1_b[out];
    }
}

// ---------------------------------------------------------------------------
// Kernel C: fused per-sample MoE. grid = 128 x 64 samples, block = 512.
// k-major smem, 2 k-phases of 250; thread tile 4 experts x 2 samples;
// FFMA2 packed over experts (w pairs free from LDS.128), h dup'd (2 mov).
// Every pipe (issue/fma/lsu/crossbar) balanced at the 128 MAC/cyc floor.
// ---------------------------------------------------------------------------
#define TS 64
#define KP 250          // k per phase
#define WR 68           // ws row stride (floats, 16B mult)
#define HR 66           // hs row stride (floats, 8B mult, 66 mod 32 = 2)
#define LR 68
#define SMEMC ((KP * WR + KP * HR + TS * LR + 256 + 64 + 4 * 64 + 64) * 4)

__global__ void __launch_bounds__(512, 1)
moe_kernel(const float* __restrict__ x, const int* __restrict__ cls_idx,
           const float* __restrict__ fc2_w, const float* __restrict__ fc2_b,
           const float* __restrict__ A_B, const float* __restrict__ A_C,
           const float* __restrict__ x_tar, float* __restrict__ out) {
    extern __shared__ float sm[];
    float* ws = sm;                 // [250][68] k-major experts
    float* hs = ws + KP * WR;       // [250][66] k-major samples
    float* Ls = hs + KP * HR;       // [64][68] logits
    float* Gs = Ls + TS * LR;       // [64][4]
    float* b2s = Gs + 256;
    float* sx0 = b2s + 64;
    float* sx1 = sx0 + 64;
    float* sd0 = sx1 + 64;
    float* sd1 = sd0 + 64;
    int* scls = (int*)(sd1 + 64);

    int tid = threadIdx.x, lane = tid & 31, warp = tid >> 5;  // 16 warps
    int base = blockIdx.x * TS;

    if (tid < 256) Gs[tid] = A_B[tid] + A_C[tid];
    if (tid < 64) b2s[tid] = fc2_b[tid];
    if (tid < TS) {
        int s = base + tid;
        float x0v = x[2 * s], x1v = x[2 * s + 1];
        sx0[tid] = x0v; sx1[tid] = x1v;
        sd0[tid] = x_tar[0] - x0v;
        sd1[tid] = x_tar[1] - x1v;
        scls[tid] = cls_idx[s];
    }

    int eg = lane & 1, sg = lane >> 1;
    int sblk = warp & 1, eblk = warp >> 1;     // eblk 0..7
    int s0 = 32 * sblk + 2 * sg;               // sample pair base
    int e0 = 8 * eblk + 4 * eg;                // expert quad base

    unsigned long long a00 = 0ull, a01 = 0ull, a10 = 0ull, a11 = 0ull;

    for (int ph = 0; ph < 2; ph++) {
        int kb = ph * KP;
        __syncthreads();  // prev-phase reads done (also covers prologue fills)
        // stage ws[k][e] (transpose of fc2_w) and fill hs[k][s]
        for (int idx = tid; idx < NEXP * KP; idx += 512) {
            int e = idx / KP, k = idx - e * KP;
            ws[k * WR + e] = fc2_w[e * FC1N + kb + k];
        }
        for (int s = warp; s < TS; s += 16) {
            int cls = scls[s];
            float xx0 = sx0[s], xx1 = sx1[s];
            const float* urow = g_u + cls * FC1N + kb;
            const float2* wxp = g_wx + kb;
            for (int k = lane; k < KP; k += 32) {
                float2 wv = wxp[k];
                float v = fmaf(xx0, wv.x, fmaf(xx1, wv.y, urow[k]));
                hs[k * HR + s] = fmaxf(v, 0.f);
            }
        }
        __syncthreads();

        const float* hp = hs + s0;
        const float* wp = ws + e0;
#pragma unroll 5
        for (int k = 0; k < KP; k++) {
            float2 hv = *(const float2*)(hp + k * HR);
            float4 wv = *(const float4*)(wp + k * WR);
            unsigned long long hd0, hd1, w01, w23;
            asm("mov.b64 %0, {%1,%1};" : "=l"(hd0) : "f"(hv.x));
            asm("mov.b64 %0, {%1,%1};" : "=l"(hd1) : "f"(hv.y));
            asm("mov.b64 %0, {%1,%2};" : "=l"(w01) : "f"(wv.x), "f"(wv.y));
            asm("mov.b64 %0, {%1,%2};" : "=l"(w23) : "f"(wv.z), "f"(wv.w));
            asm("fma.rn.f32x2 %0, %1, %2, %0;" : "+l"(a00) : "l"(w01), "l"(hd0));
            asm("fma.rn.f32x2 %0, %1, %2, %0;" : "+l"(a01) : "l"(w23), "l"(hd0));
            asm("fma.rn.f32x2 %0, %1, %2, %0;" : "+l"(a10) : "l"(w01), "l"(hd1));
            asm("fma.rn.f32x2 %0, %1, %2, %0;" : "+l"(a11) : "l"(w23), "l"(hd1));
        }
    }

    // unpack logits (+bias) into Ls[s][e]
    {
        float v0, v1, v2, v3, u0, u1, u2, u3;
        asm("mov.b64 {%0,%1}, %2;" : "=f"(v0), "=f"(v1) : "l"(a00));
        asm("mov.b64 {%0,%1}, %2;" : "=f"(v2), "=f"(v3) : "l"(a01));
        asm("mov.b64 {%0,%1}, %2;" : "=f"(u0), "=f"(u1) : "l"(a10));
        asm("mov.b64 {%0,%1}, %2;" : "=f"(u2), "=f"(u3) : "l"(a11));
        float* L0 = Ls + s0 * LR + e0;
        float* L1 = Ls + (s0 + 1) * LR + e0;
        float b0 = b2s[e0], b1 = b2s[e0 + 1], b2 = b2s[e0 + 2], b3 = b2s[e0 + 3];
        L0[0] = v0 + b0; L0[1] = v1 + b1; L0[2] = v2 + b2; L0[3] = v3 + b3;
        L1[0] = u0 + b0; L1[1] = u1 + b1; L1[2] = u2 + b2; L1[3] = u3 + b3;
    }
    __syncthreads();

    // softmax over 64 + expert mix; warp-per-sample (2 experts per lane)
    for (int s = warp; s < TS; s += 16) {
        float l0 = Ls[s * LR + lane];
        float l1 = Ls[s * LR + 32 + lane];
        float m = fmaxf(l0, l1);
#pragma unroll
        for (int off = 16; off; off >>= 1) m = fmaxf(m, __shfl_xor_sync(~0u, m, off));
        float ee0 = __expf(l0 - m), ee1 = __expf(l1 - m);
        float d0 = sd0[s], d1 = sd1[s];
        const float* G0 = Gs + lane * 4;
        const float* G1 = Gs + (lane + 32) * 4;
        float y0 = ee0 * (G0[0] * d0 + G0[1] * d1) + ee1 * (G1[0] * d0 + G1[1] * d1);
        float y1 = ee0 * (G0[2] * d0 + G0[3] * d1) + ee1 * (G1[2] * d0 + G1[3] * d1);
        float Z = ee0 + ee1;
#pragma unroll
        for (int off = 16; off; off >>= 1) {
            y0 += __shfl_xor_sync(~0u, y0, off);
            y1 += __shfl_xor_sync(~0u, y1, off);
            Z += __shfl_xor_sync(~0u, Z, off);
        }
        if (lane == 0) {
            float inv = 1.f / Z;
            out[2 * (base + s) + 0] = y0 * inv;
            out[2 * (base + s) + 1] = y1 * inv;
        }
    }
}

// ---------------------------------------------------------------------------
extern "C" void kernel_launch(void* const* d_in, const int* in_sizes, int n_in,
                              void* d_out, int out_size) {
    const float* x       = (const float*)d_in[0];
    const int*   cls     = (const int*)d_in[1];
    const float* images  = (const float*)d_in[2];
    const float* conv1_w = (const float*)d_in[3];
    const float* conv1_b = (const float*)d_in[4];
    const float* conv2_w = (const float*)d_in[5];
    const float* conv2_b = (const float*)d_in[6];
    const float* fc1_w   = (const float*)d_in[7];
    const float* fc1_b   = (const float*)d_in[8];
    const float* fc2_w   = (const float*)d_in[9];
    const float* fc2_b   = (const float*)d_in[10];
    const float* A_B     = (const float*)d_in[11];
    const float* A_C     = (const float*)d_in[12];
    const float* x_tar   = (const float*)d_in[13];
    float* out = (float*)d_out;

    cudaFuncSetAttribute(fc1_kernel, cudaFuncAttributeMaxDynamicSharedMemorySize,
                         FC1SMEM);
    cudaFuncSetAttribute(moe_kernel, cudaFuncAttributeMaxDynamicSharedMemorySize,
                         SMEMC);

    conv1_kernel<<<N_CLASSES * 5, 512>>>(images, conv1_w, conv1_b, fc1_w);
    conv2_kernel<<<N_CLASSES * 10, 256>>>(conv2_w, conv2_b);
    fc1_kernel<<<128, 256, FC1SMEM>>>(fc1_w, fc1_b);
    moe_kernel<<<BATCH / TS, 512, SMEMC>>>(x, cls, fc2_w, fc2_b, A_B, A_C, x_tar, out);
    (void)in_sizes; (void)n_in; (void)out_size;
}